// round 5
// baseline (speedup 1.0000x reference)
#include <cuda_runtime.h>
#include <cuda_bf16.h>
#include <math.h>

// LocalPearsonDepthLoss — one warp per patch, 128-thread blocks.
//   Lane l reads column l of each 32-float row (coalesced 128B per image).
//   5 running sums -> warp shuffle reduce -> closed-form Pearson.
//   4 warps/block, grid=2048: fine-grained placement (13.8 blocks/SM) for
//   high occupancy and small wave tail. Single-kernel final reduction via
//   last-block-done pattern (deterministic across graph replays).

#define W_IMG 4096
#define BOX   32
#define PATCH 1024.0f
#define MAX_BLOCKS 8192

__device__ float        g_partials[MAX_BLOCKS];
__device__ unsigned int g_done = 0;

__global__ __launch_bounds__(128) void pearson_loss_kernel(
    const float* __restrict__ pred,
    const float* __restrict__ gt,
    const int*   __restrict__ x0,
    const int*   __restrict__ y0,
    float* __restrict__ out,
    int n_corr)
{
    const int warp_global = (blockIdx.x * blockDim.x + threadIdx.x) >> 5;
    const int lane = threadIdx.x & 31;
    const int wid_in_blk = threadIdx.x >> 5;

    float contrib = 0.0f;

    if (warp_global < n_corr) {
        const int xb = x0[warp_global];
        const int yb = y0[warp_global];
        const size_t base = (size_t)xb * W_IMG + yb + lane;
        const float* __restrict__ pp = pred + base;
        const float* __restrict__ gp = gt + base;

        float sp = 0.f, sg = 0.f, spp = 0.f, sgg = 0.f, spg = 0.f;

        #pragma unroll 8
        for (int r = 0; r < BOX; r++) {
            float p = __ldg(pp + (size_t)r * W_IMG);
            float g = __ldg(gp + (size_t)r * W_IMG);
            sp  += p;
            sg  += g;
            spp = fmaf(p, p, spp);
            sgg = fmaf(g, g, sgg);
            spg = fmaf(p, g, spg);
        }

        #pragma unroll
        for (int off = 16; off > 0; off >>= 1) {
            sp  += __shfl_xor_sync(0xffffffffu, sp,  off);
            sg  += __shfl_xor_sync(0xffffffffu, sg,  off);
            spp += __shfl_xor_sync(0xffffffffu, spp, off);
            sgg += __shfl_xor_sync(0xffffffffu, sgg, off);
            spg += __shfl_xor_sync(0xffffffffu, spg, off);
        }

        if (lane == 0) {
            const float P = PATCH;
            float mp = sp / P;
            float mg = sg / P;
            float varp = (spp - P * mp * mp) * (1.0f / (P - 1.0f));
            float varg = (sgg - P * mg * mg) * (1.0f / (P - 1.0f));
            float stdp = sqrtf(fmaxf(varp, 0.0f)) + 1e-6f;
            float stdg = sqrtf(fmaxf(varg, 0.0f)) + 1e-6f;
            float cov = spg / P - mp * mg;
            float co = cov / (stdp * stdg);
            contrib = (1.0f - co) / (float)n_corr;
        }
    }

    // Block reduce (4 warps) then last-block final reduction.
    __shared__ float warp_sums[4];
    __shared__ bool  is_last;
    if (lane == 0) warp_sums[wid_in_blk] = contrib;
    __syncthreads();
    if (threadIdx.x == 0) {
        float bs = warp_sums[0] + warp_sums[1] + warp_sums[2] + warp_sums[3];
        g_partials[blockIdx.x] = bs;
        __threadfence();                       // release our partial
        unsigned int old = atomicAdd(&g_done, 1u);
        is_last = (old == gridDim.x - 1);
        if (is_last) __threadfence();          // acquire all partials
    }
    __syncthreads();

    if (is_last) {
        float v = 0.0f;
        for (int i = threadIdx.x; i < gridDim.x; i += blockDim.x)
            v += g_partials[i];
        #pragma unroll
        for (int off = 16; off > 0; off >>= 1)
            v += __shfl_xor_sync(0xffffffffu, v, off);
        if (lane == 0) warp_sums[wid_in_blk] = v;
        __syncthreads();
        if (threadIdx.x == 0) {
            out[0] = warp_sums[0] + warp_sums[1] + warp_sums[2] + warp_sums[3];
            g_done = 0;   // reset for next graph replay
        }
    }
}

extern "C" void kernel_launch(void* const* d_in, const int* in_sizes, int n_in,
                              void* d_out, int out_size)
{
    const float* pred = (const float*)d_in[0];
    const float* gt   = (const float*)d_in[1];
    const int*   x0   = (const int*)d_in[2];
    const int*   y0   = (const int*)d_in[3];
    float* out = (float*)d_out;

    const int n_corr = in_sizes[2];

    const int threads = 128;                    // 4 warps/block, 1 warp/patch
    const int warps_per_blk = threads / 32;
    const int blocks = (n_corr + warps_per_blk - 1) / warps_per_blk;
    pearson_loss_kernel<<<blocks, threads>>>(pred, gt, x0, y0, out, n_corr);
}